// round 2
// baseline (speedup 1.0000x reference)
#include <cuda_runtime.h>
#include <math.h>

#define NPFS   4
#define NMODES 512
#define NP     256
#define BATCH  128
#define NTASK  (NPFS * BATCH)   // 512 independent pfaffians
#define NT     512              // threads per CTA

// Padded lower-triangle size: sum_{s<256} ceil4(s) = 32640 + 384 = 33024 floats
#define T_ELEMS 33024
#define SMEM_BYTES ((T_ELEMS + 1064) * 4)

__device__ float g_sgn[NTASK];
__device__ float g_la[NTASK];

// Row r of the strictly-lower triangle starts at rowoff(r), 16B-aligned.
// rowoff(r) = r(r-1)/2 + 6*(r>>2) + lut[r&3], lut = {0,0,3,5}
__device__ __forceinline__ int rowoff(int r) {
    return ((r * (r - 1)) >> 1) + 6 * (r >> 2) + ((0x5300 >> ((r & 3) << 2)) & 0xF);
}

__global__ __launch_bounds__(NT, 1)
void pf_kernel(const float* __restrict__ F, const int* __restrict__ idx)
{
    extern __shared__ float sh[];
    float* Tm   = sh;                           // [T_ELEMS] lower triangle, A[r][c], r>c
    float* colk = sh + T_ELEMS;                 // [256] cached column k
    float* tau  = sh + T_ELEMS + 256;           // [256]
    float* vv   = sh + T_ELEMS + 512;           // [256]
    int*   idxs = (int*)  (sh + T_ELEMS + 768); // [256]
    float* redv = sh + T_ELEMS + 1024;          // [16]
    int*   redi = (int*)  (sh + T_ELEMS + 1040);// [16]
    int*   s_kp = (int*)  (sh + T_ELEMS + 1056);
    float* s_pv = sh + T_ELEMS + 1057;

    const int task = blockIdx.x;          // 0..511
    const int b = task >> 2, s = task & 3;
    const float* Fb = F + (size_t)s * NMODES * NMODES;

    const int tid  = threadIdx.x;
    const int lane = tid & 31;
    const int w    = tid >> 5;            // warp 0..15
    const int r    = tid & 255;           // row owned by this thread
    const int h    = tid >> 8;            // 0/1: column-block interleave half

    if (tid < NP) idxs[tid] = idx[b * NP + tid];
    __syncthreads();

    // ---- Gather + antisymmetrize: Tm[r][c] = 0.5*(F[ir,ic] - F[ic,ir]), r>c ----
    // Sweep 1 (row-gather, coalesced-ish): Tm[a][c] = F[i_a, i_c]
    for (int a = w; a < NP; a += 16) {
        const float* Frow = Fb + (size_t)idxs[a] * NMODES;
        const int base = rowoff(a);
        for (int c = lane; c < a; c += 32)
            Tm[base + c] = Frow[idxs[c]];
    }
    __syncthreads();
    // Sweep 2 (also row-gather, over the transpose term): per column c
    for (int c = w; c < NP; c += 16) {
        const float* Frow = Fb + (size_t)idxs[c] * NMODES;
        for (int rr = c + 1 + lane; rr < NP; rr += 32) {
            const int o = rowoff(rr) + c;
            Tm[o] = 0.5f * (Tm[o] - Frow[idxs[rr]]);
        }
    }
    __syncthreads();

    float sgn = 1.f, la = 0.f;   // maintained by tid==0 only

    for (int k = 0; k <= NP - 2; k += 2) {
        // ---- Phase 1: read column k, block argmax |A[r][k]| over r>k ----
        float val = -2.f; int bi = tid;
        if (tid < NP && r > k) {
            const float cv = Tm[rowoff(r) + k];
            colk[r] = cv;
            val = fabsf(cv);
        }
        #pragma unroll
        for (int o = 16; o; o >>= 1) {
            const float ov = __shfl_down_sync(0xffffffffu, val, o);
            const int   oi = __shfl_down_sync(0xffffffffu, bi, o);
            if (ov > val || (ov == val && oi < bi)) { val = ov; bi = oi; }
        }
        if (lane == 0) { redv[w] = val; redi[w] = bi; }
        __syncthreads();
        if (w == 0) {
            float bv = (lane < 16) ? redv[lane] : -3.f;
            int   b2 = (lane < 16) ? redi[lane] : 0;
            #pragma unroll
            for (int o = 8; o; o >>= 1) {
                const float ov = __shfl_down_sync(0xffffffffu, bv, o);
                const int   oi = __shfl_down_sync(0xffffffffu, b2, o);
                if (ov > bv || (ov == bv && oi < b2)) { bv = ov; b2 = oi; }
            }
            if (lane == 0) {
                // pivot value AFTER the (pending) swap: A'[k][k+1] = -A[kp][k]
                const float piv = -colk[b2];
                s_kp[0] = b2;
                s_pv[0] = piv;
                if (b2 != k + 1) sgn = -sgn;
                sgn *= (piv > 0.f) ? 1.f : ((piv < 0.f) ? -1.f : 0.f);
                la  += logf(fabsf(piv));
            }
        }
        __syncthreads();
        const int   kp  = s_kp[0];
        const float piv = s_pv[0];
        const int   i1  = k + 1;

        // ---- Phase 2: skew row/col swap i1 <-> kp (only live regions) ----
        if (kp != i1) {
            if (tid < NP) {
                const int ss = tid;
                if (ss > i1 && ss < kp) {
                    const float t1 = Tm[rowoff(ss) + i1];
                    const float t2 = Tm[rowoff(kp) + ss];
                    Tm[rowoff(ss) + i1] = -t2;
                    Tm[rowoff(kp) + ss] = -t1;
                } else if (ss > kp) {
                    const float t1 = Tm[rowoff(ss) + i1];
                    Tm[rowoff(ss) + i1] = Tm[rowoff(ss) + kp];
                    Tm[rowoff(ss) + kp] = t1;
                } else if (ss == kp) {
                    Tm[rowoff(kp) + i1] = -Tm[rowoff(kp) + i1];
                    const float t = colk[i1]; colk[i1] = colk[kp]; colk[kp] = t;
                }
            }
            __syncthreads();
        }

        // ---- Phase 3: tau = A[:,k]/piv, v = A[:,k+1]  (rows >= k+2) ----
        if (tid < NP && r >= k + 2) {
            tau[r] = colk[r] / piv;
            vv[r]  = Tm[rowoff(r) + i1];
        }
        __syncthreads();

        // ---- Phase 4: rank-2 skew update on lower triangle ----
        // A[r][c] = (A[r][c] - tau[r]*v[c]) + v[r]*tau[c],   r > c >= k+2
        const int cbeg = k + 2;
        if (r > cbeg) {
            const int   base = rowoff(r);
            const float vr  = vv[r];
            const float ntr = -tau[r];
            const int   cA  = (cbeg + 3) & ~3;   // first 16B-aligned column
            if (h == 0) {                         // scalar prologue
                const int ce = cA < r ? cA : r;
                for (int c = cbeg; c < ce; ++c)
                    Tm[base + c] = fmaf(vr, tau[c], fmaf(ntr, vv[c], Tm[base + c]));
            }
            // vectorized body, 4-col blocks interleaved between halves
            for (int c = cA + 4 * h; c + 4 <= r; c += 8) {
                float4 a        = *reinterpret_cast<float4*>(&Tm[base + c]);
                const float4 tc = *reinterpret_cast<const float4*>(&tau[c]);
                const float4 vc = *reinterpret_cast<const float4*>(&vv[c]);
                a.x = fmaf(vr, tc.x, fmaf(ntr, vc.x, a.x));
                a.y = fmaf(vr, tc.y, fmaf(ntr, vc.y, a.y));
                a.z = fmaf(vr, tc.z, fmaf(ntr, vc.z, a.z));
                a.w = fmaf(vr, tc.w, fmaf(ntr, vc.w, a.w));
                *reinterpret_cast<float4*>(&Tm[base + c]) = a;
            }
            if (h == 1 && r > cA) {               // scalar tail
                for (int c = cA + ((r - cA) & ~3); c < r; ++c)
                    Tm[base + c] = fmaf(vr, tau[c], fmaf(ntr, vv[c], Tm[base + c]));
            }
        }
        __syncthreads();
    }

    if (tid == 0) { g_sgn[task] = sgn; g_la[task] = la; }
}

// Signed logsumexp over the 4 pfaffian components per batch element.
__global__ void combine_kernel(float* __restrict__ out)
{
    const int bidx = threadIdx.x;
    if (bidx < BATCH) {
        const float l0 = g_la[4 * bidx + 0], l1 = g_la[4 * bidx + 1];
        const float l2 = g_la[4 * bidx + 2], l3 = g_la[4 * bidx + 3];
        const float m = fmaxf(fmaxf(l0, l1), fmaxf(l2, l3));
        const float val = g_sgn[4 * bidx + 0] * expf(l0 - m)
                        + g_sgn[4 * bidx + 1] * expf(l1 - m)
                        + g_sgn[4 * bidx + 2] * expf(l2 - m)
                        + g_sgn[4 * bidx + 3] * expf(l3 - m);
        out[bidx]         = (val > 0.f) ? 1.f : ((val < 0.f) ? -1.f : 0.f);
        out[BATCH + bidx] = m + logf(fabsf(val));
    }
}

extern "C" void kernel_launch(void* const* d_in, const int* in_sizes, int n_in,
                              void* d_out, int out_size)
{
    (void)in_sizes; (void)n_in; (void)out_size;
    const float* F   = (const float*)d_in[0];
    const int*   idx = (const int*)d_in[1];
    float*       out = (float*)d_out;

    cudaFuncSetAttribute(pf_kernel, cudaFuncAttributeMaxDynamicSharedMemorySize, SMEM_BYTES);
    pf_kernel<<<NTASK, NT, SMEM_BYTES>>>(F, idx);
    combine_kernel<<<1, 128>>>(out);
}

// round 3
// speedup vs baseline: 1.5377x; 1.5377x over previous
#include <cuda_runtime.h>
#include <math.h>

#define NPFS   4
#define NMODES 512
#define NP     256
#define BATCH  128
#define NTASK  (NPFS * BATCH)
#define NT     512
#define PB     8                 // pivot pairs per panel (panel = 16 columns)

// Padded lower-triangle: sum_{s<256} ceil4(s) = 33024 floats, rows 16B-aligned
#define T_ELEMS 33024
#define OFF_VT   33024           // tau vectors  [PB][256]
#define OFF_UT   35072           // v   vectors  [PB][256]
#define OFF_COLK 37120
#define OFF_IDXS 37376
#define OFF_REDK 37632           // 16 x u64 (as 32 floats)
#define OFF_SKP  37664
#define OFF_SPV  37665
#define SMEM_BYTES ((37672) * 4)

__device__ float g_sgn[NTASK];
__device__ float g_la[NTASK];

__device__ __forceinline__ int rowoff(int r) {
    return ((r * (r - 1)) >> 1) + 6 * (r >> 2) + ((0x5300 >> ((r & 3) << 2)) & 0xF);
}

__device__ __forceinline__ unsigned long long pk2(float x) {
    unsigned long long r;
    asm("mov.b64 %0, {%1, %1};" : "=l"(r) : "f"(x));
    return r;
}
__device__ __forceinline__ unsigned long long fma2(unsigned long long a,
                                                   unsigned long long b,
                                                   unsigned long long c) {
    unsigned long long d;
    asm("fma.rn.f32x2 %0, %1, %2, %3;" : "=l"(d) : "l"(a), "l"(b), "l"(c));
    return d;
}

// SMSP-balanced row-block pairing: SMSP s owns blocks {P[s], P[s+4]}, sums = 7
__constant__ int c_pairperm[8] = {0, 2, 3, 1, 7, 5, 4, 6};

__global__ __launch_bounds__(NT, 1)
void pf_kernel(const float* __restrict__ F, const int* __restrict__ idx)
{
    extern __shared__ float sh[];
    float* Tm   = sh;
    float* Vt   = sh + OFF_VT;    // tau_p at Vt[p*256 + r]
    float* Ut   = sh + OFF_UT;    // v_p   at Ut[p*256 + r]
    float* colk = sh + OFF_COLK;
    int*   idxs = (int*)(sh + OFF_IDXS);
    unsigned long long* redk = (unsigned long long*)(sh + OFF_REDK);
    int*   s_kp = (int*)(sh + OFF_SKP);
    float* s_pv = sh + OFF_SPV;

    const int task = blockIdx.x;
    const int b = task >> 2, s = task & 3;
    const float* Fb = F + (size_t)s * NMODES * NMODES;

    const int tid  = threadIdx.x;
    const int lane = tid & 31;
    const int w    = tid >> 5;
    const int h    = tid >> 8;                      // column-parity half
    const int rb   = 32 * c_pairperm[w & 7] + lane; // balanced trailing row

    if (tid < NP) idxs[tid] = idx[b * NP + tid];
    __syncthreads();

    // ---- Gather + antisymmetrize lower triangle ----
    for (int a = w; a < NP; a += 16) {
        const float* Frow = Fb + (size_t)idxs[a] * NMODES;
        const int base = rowoff(a);
        for (int c = lane; c < a; c += 32)
            Tm[base + c] = Frow[idxs[c]];
    }
    __syncthreads();
    for (int c = w; c < NP; c += 16) {
        const float* Frow = Fb + (size_t)idxs[c] * NMODES;
        for (int rr = c + 1 + lane; rr < NP; rr += 32) {
            const int o = rowoff(rr) + c;
            Tm[o] = 0.5f * (Tm[o] - Frow[idxs[rr]]);
        }
    }
    __syncthreads();

    float sgn = 1.f, la = 0.f;   // thread 0 only

    for (int kb = 0; kb < NP; kb += 2 * PB) {
        // ================= panel factorization =================
        for (int p = 0; p < PB; ++p) {
            const int k = kb + 2 * p;

            // -- lazy column k + argmax key --
            unsigned long long key = 0ull;
            if (tid < NP && tid > k) {
                float c0 = Tm[rowoff(tid) + k];
                for (int q = 0; q < p; ++q)
                    c0 += Ut[q * 256 + tid] * Vt[q * 256 + k]
                        - Vt[q * 256 + tid] * Ut[q * 256 + k];
                colk[tid] = c0;
                key = ((unsigned long long)__float_as_uint(fabsf(c0)) << 32)
                    | (unsigned)(NP - 1 - tid);
            }
            #pragma unroll
            for (int o = 16; o; o >>= 1) {
                const unsigned long long ok = __shfl_down_sync(0xffffffffu, key, o);
                if (ok > key) key = ok;
            }
            if (lane == 0) redk[w] = key;
            __syncthreads();                                   // BAR1
            if (w == 0) {
                unsigned long long kk = (lane < 16) ? redk[lane] : 0ull;
                #pragma unroll
                for (int o = 8; o; o >>= 1) {
                    const unsigned long long ok = __shfl_down_sync(0xffffffffu, kk, o);
                    if (ok > kk) kk = ok;
                }
                if (lane == 0) {
                    const int b2 = NP - 1 - (int)(kk & 0xffffffffu);
                    const float piv = -colk[b2];               // A'[k][k+1]
                    s_kp[0] = b2; s_pv[0] = piv;
                    if (b2 != k + 1) sgn = -sgn;
                    sgn *= (piv > 0.f) ? 1.f : ((piv < 0.f) ? -1.f : 0.f);
                    la  += logf(fabsf(piv));
                }
            }
            __syncthreads();                                   // BAR2
            const int   kp  = s_kp[0];
            const float piv = s_pv[0];
            const int   i1  = k + 1;

            // -- eager skew swap i1 <-> kp (A, colk, U/V rows) --
            if (kp != i1) {
                if (tid < NP) {
                    const int ss = tid;
                    if (ss > i1 && ss < kp) {
                        const float t1 = Tm[rowoff(ss) + i1];
                        const float t2 = Tm[rowoff(kp) + ss];
                        Tm[rowoff(ss) + i1] = -t2;
                        Tm[rowoff(kp) + ss] = -t1;
                    } else if (ss > kp) {
                        const float t1 = Tm[rowoff(ss) + i1];
                        Tm[rowoff(ss) + i1] = Tm[rowoff(ss) + kp];
                        Tm[rowoff(ss) + kp] = t1;
                    } else if (ss == kp) {
                        Tm[rowoff(kp) + i1] = -Tm[rowoff(kp) + i1];
                        const float t = colk[i1]; colk[i1] = colk[kp]; colk[kp] = t;
                    }
                } else if (tid - NP < p) {
                    const int q = tid - NP;
                    float t;
                    t = Ut[q * 256 + i1]; Ut[q * 256 + i1] = Ut[q * 256 + kp]; Ut[q * 256 + kp] = t;
                    t = Vt[q * 256 + i1]; Vt[q * 256 + i1] = Vt[q * 256 + kp]; Vt[q * 256 + kp] = t;
                }
                __syncthreads();                               // BAR3 (conditional)
            }

            // -- tau_p = col_k/piv ; v_p = lazy column k+1 --
            if (tid < NP) {
                if (tid >= k + 2) {
                    const float t = colk[tid] / piv;
                    float c1 = Tm[rowoff(tid) + i1];
                    for (int q = 0; q < p; ++q)
                        c1 += Ut[q * 256 + tid] * Vt[q * 256 + i1]
                            - Vt[q * 256 + tid] * Ut[q * 256 + i1];
                    Vt[p * 256 + tid] = t;
                    Ut[p * 256 + tid] = c1;
                } else {
                    Vt[p * 256 + tid] = 0.f;
                    Ut[p * 256 + tid] = 0.f;
                }
            }
            __syncthreads();                                   // BAR4
        }

        // ================= rank-16 trailing update =================
        const int cbeg = kb + 2 * PB;                          // multiple of 16
        if (cbeg < NP) {
            if (rb > cbeg) {
                const int base = rowoff(rb);
                unsigned long long vr2[PB], ntr2[PB];
                #pragma unroll
                for (int p = 0; p < PB; ++p) {
                    vr2[p]  = pk2(Ut[p * 256 + rb]);
                    ntr2[p] = pk2(-Vt[p * 256 + rb]);
                }
                for (int c = cbeg + 4 * h; c + 4 <= rb; c += 8) {
                    ulonglong2 av = *reinterpret_cast<ulonglong2*>(&Tm[base + c]);
                    #pragma unroll
                    for (int p = 0; p < PB; ++p) {
                        const ulonglong2 tc = *reinterpret_cast<const ulonglong2*>(&Vt[p * 256 + c]);
                        const ulonglong2 vc = *reinterpret_cast<const ulonglong2*>(&Ut[p * 256 + c]);
                        av.x = fma2(vr2[p], tc.x, av.x);
                        av.x = fma2(ntr2[p], vc.x, av.x);
                        av.y = fma2(vr2[p], tc.y, av.y);
                        av.y = fma2(ntr2[p], vc.y, av.y);
                    }
                    *reinterpret_cast<ulonglong2*>(&Tm[base + c]) = av;
                }
                if (h == 1) {                                  // scalar tail (< 4 cols)
                    float vrf[PB], trf[PB];
                    #pragma unroll
                    for (int p = 0; p < PB; ++p) {
                        vrf[p] = Ut[p * 256 + rb];
                        trf[p] = Vt[p * 256 + rb];
                    }
                    for (int c = cbeg + ((rb - cbeg) & ~3); c < rb; ++c) {
                        float a = Tm[base + c];
                        #pragma unroll
                        for (int p = 0; p < PB; ++p)
                            a = fmaf(vrf[p], Vt[p * 256 + c],
                                fmaf(-trf[p], Ut[p * 256 + c], a));
                        Tm[base + c] = a;
                    }
                }
            }
            __syncthreads();                                   // BAR5
        }
    }

    if (tid == 0) { g_sgn[task] = sgn; g_la[task] = la; }
}

__global__ void combine_kernel(float* __restrict__ out)
{
    const int bidx = threadIdx.x;
    if (bidx < BATCH) {
        const float l0 = g_la[4 * bidx + 0], l1 = g_la[4 * bidx + 1];
        const float l2 = g_la[4 * bidx + 2], l3 = g_la[4 * bidx + 3];
        const float m = fmaxf(fmaxf(l0, l1), fmaxf(l2, l3));
        const float val = g_sgn[4 * bidx + 0] * expf(l0 - m)
                        + g_sgn[4 * bidx + 1] * expf(l1 - m)
                        + g_sgn[4 * bidx + 2] * expf(l2 - m)
                        + g_sgn[4 * bidx + 3] * expf(l3 - m);
        out[bidx]         = (val > 0.f) ? 1.f : ((val < 0.f) ? -1.f : 0.f);
        out[BATCH + bidx] = m + logf(fabsf(val));
    }
}

extern "C" void kernel_launch(void* const* d_in, const int* in_sizes, int n_in,
                              void* d_out, int out_size)
{
    (void)in_sizes; (void)n_in; (void)out_size;
    const float* F   = (const float*)d_in[0];
    const int*   idx = (const int*)d_in[1];
    float*       out = (float*)d_out;

    cudaFuncSetAttribute(pf_kernel, cudaFuncAttributeMaxDynamicSharedMemorySize, SMEM_BYTES);
    pf_kernel<<<NTASK, NT, SMEM_BYTES>>>(F, idx);
    combine_kernel<<<1, 128>>>(out);
}